// round 14
// baseline (speedup 1.0000x reference)
#include <cuda_runtime.h>

// AvgSeq: out[b,s,d] = cumsum_s(x[b,s,d]) / (s+1)
// Fused single-kernel chained scan (StreamScan style, flag=2 only).
// B=16, S=8192, D=256, fp32.
//
// Grid = (NC=32, B=16) = 512 blocks x 64 threads -> ALL blocks co-resident
// (148 SMs, ~3.5 blocks/SM), so waiting on a predecessor block can never
// deadlock. Each block sums its chunk, chains the prefix through one flag,
// then re-reads its (L2-hot) chunk to emit output.

#define B 16
#define S 8192
#define D 256
#define DV (D / 4)       // 64 float4 lanes
#define NC 32            // seq chunks per batch
#define CLEN (S / NC)    // 256 seq steps per chunk

__device__ float4 g_pref[B * NC * DV];   // inclusive prefix vectors
__device__ int    g_flag[B * NC];        // 0 = invalid, 2 = prefix ready

// Reset flags each launch (graph-safe, deterministic).
__global__ void init_state() {
    int i = blockIdx.x * blockDim.x + threadIdx.x;
    if (i < B * NC) g_flag[i] = 0;
}

__global__ void __launch_bounds__(DV) scan_kernel(const float4* __restrict__ x,
                                                  float4* __restrict__ y) {
    __shared__ float s_recip[CLEN];
    const int t = threadIdx.x;           // float4 lane
    const int c = blockIdx.x;            // chunk within batch
    const int b = blockIdx.y;
    const int s0 = c * CLEN;

    // Reciprocal table: 4 per thread (CLEN = 4 * DV).
#pragma unroll
    for (int k = 0; k < CLEN / DV; ++k) {
        const int s = k * DV + t;
        s_recip[s] = __fdividef(1.0f, (float)(s0 + s + 1));
    }

    const size_t base = ((size_t)b * S + (size_t)s0) * DV + t;
    const float4* p = x + base;

    // Phase 1: stream-sum the chunk (populates L2 for the emit re-read).
    float4 agg = make_float4(0.f, 0.f, 0.f, 0.f);
#pragma unroll 8
    for (int s = 0; s < CLEN; ++s) {
        const float4 v = p[(size_t)s * DV];
        agg.x += v.x; agg.y += v.y; agg.z += v.z; agg.w += v.w;
    }

    // Phase 2: chain the inclusive prefix through the single predecessor.
    float4 excl = make_float4(0.f, 0.f, 0.f, 0.f);
    if (c > 0) {
        if (t == 0) {
            // Spin on the immediate predecessor's flag (proven primitive).
            while (atomicAdd(&g_flag[b * NC + c - 1], 0) != 2) { }
        }
        __syncthreads();
        __threadfence();   // acquire: order flag observation before data read
        const float4* src = &g_pref[(b * NC + c - 1) * DV + t];
        float4 e;
        asm volatile("ld.global.cg.v4.f32 {%0,%1,%2,%3}, [%4];"
                     : "=f"(e.x), "=f"(e.y), "=f"(e.z), "=f"(e.w) : "l"(src));
        excl = e;
    }

    // Publish own inclusive prefix immediately (before the emit pass) so the
    // successor's wait is not gated on our output stores.
    float4 incl;
    incl.x = excl.x + agg.x; incl.y = excl.y + agg.y;
    incl.z = excl.z + agg.z; incl.w = excl.w + agg.w;
    g_pref[(b * NC + c) * DV + t] = incl;
    __threadfence();
    __syncthreads();
    if (t == 0) atomicExch(&g_flag[b * NC + c], 2);

    // Phase 3: re-read the (L2-hot) chunk, scan, scale, evict-first store.
    float4 run = excl;
    float4* q = y + base;
#pragma unroll 4
    for (int s = 0; s < CLEN; ++s) {
        const float4 v = p[(size_t)s * DV];
        run.x += v.x; run.y += v.y; run.z += v.z; run.w += v.w;
        const float r = s_recip[s];
        float4 o;
        o.x = run.x * r; o.y = run.y * r; o.z = run.z * r; o.w = run.w * r;
        __stcs(q + (size_t)s * DV, o);
    }
}

extern "C" void kernel_launch(void* const* d_in, const int* in_sizes, int n_in,
                              void* d_out, int out_size) {
    const float4* x = (const float4*)d_in[0];
    float4* y = (float4*)d_out;

    init_state<<<(B * NC + 255) / 256, 256>>>();
    dim3 grid(NC, B);
    scan_kernel<<<grid, DV>>>(x, y);
}

// round 15
// speedup vs baseline: 1.0374x; 1.0374x over previous
#include <cuda_runtime.h>

// AvgSeq: out[b,s,d] = cumsum_s(x[b,s,d]) / (s+1)
// Fused single-kernel chained scan, 256-thread blocks for full streaming
// occupancy. B=16, S=8192, D=256, fp32.
//
// Grid = (NC=32, B=16) = 512 blocks x 256 threads -> all blocks co-resident
// (131K threads << 303K resident capacity), so the predecessor chain can
// never deadlock. Thread (sub, lane): sub = t/64 picks a contiguous 64-step
// sub-range of the 256-step chunk, lane = t%64 picks the float4 d-lane.

#define B 16
#define S 8192
#define D 256
#define DV (D / 4)        // 64 float4 lanes
#define NC 32             // chunks per batch
#define CLEN (S / NC)     // 256 seq steps per chunk
#define NSUB 4            // sub-ranges per chunk
#define SUBLEN (CLEN / NSUB)  // 64 steps per thread

__device__ float4 g_pref[B * NC * DV];   // inclusive prefix vectors
__device__ int    g_flag[B * NC];        // 0 = invalid, 2 = prefix ready

__global__ void init_state() {
    int i = blockIdx.x * blockDim.x + threadIdx.x;
    if (i < B * NC) g_flag[i] = 0;
}

__global__ void __launch_bounds__(256) scan_kernel(const float4* __restrict__ x,
                                                   float4* __restrict__ y) {
    __shared__ float4 s_part[NSUB][DV];   // per-(sub,lane) sub-range sums
    __shared__ float4 s_carry[DV];        // predecessor inclusive prefix
    __shared__ float  s_recip[CLEN];

    const int t    = threadIdx.x;
    const int lane = t & (DV - 1);
    const int sub  = t >> 6;
    const int c    = blockIdx.x;          // chunk within batch
    const int b    = blockIdx.y;
    const int s0   = c * CLEN;

    // Reciprocal table: one per thread (CLEN == 256 == blockDim).
    s_recip[t] = __fdividef(1.0f, (float)(s0 + t + 1));

    const size_t base =
        ((size_t)b * S + (size_t)s0 + (size_t)sub * SUBLEN) * DV + lane;
    const float4* p = x + base;

    // Phase 1: sum this thread's 64-step sub-range (64 x LDG.128).
    float4 a = make_float4(0.f, 0.f, 0.f, 0.f);
#pragma unroll 8
    for (int s = 0; s < SUBLEN; ++s) {
        const float4 v = p[(size_t)s * DV];
        a.x += v.x; a.y += v.y; a.z += v.z; a.w += v.w;
    }
    s_part[sub][lane] = a;
    __syncthreads();

    // Intra-chunk exclusive offset for this sub-range (<=3 smem reads).
    float4 off = make_float4(0.f, 0.f, 0.f, 0.f);
#pragma unroll
    for (int k = 0; k < NSUB; ++k) {
        if (k < sub) {
            const float4 q = s_part[k][lane];
            off.x += q.x; off.y += q.y; off.z += q.z; off.w += q.w;
        }
    }

    // Phase 2: chain through the immediate predecessor.
    if (c > 0) {
        if (t == 0) {
            while (atomicAdd(&g_flag[b * NC + c - 1], 0) != 2) { }
        }
        __syncthreads();
        __threadfence();   // acquire: flag observation before data reads
        if (t < DV) {
            const float4* src = &g_pref[(b * NC + c - 1) * DV + t];
            float4 e;
            asm volatile("ld.global.cg.v4.f32 {%0,%1,%2,%3}, [%4];"
                         : "=f"(e.x), "=f"(e.y), "=f"(e.z), "=f"(e.w)
                         : "l"(src));
            s_carry[t] = e;
        }
    } else {
        if (t < DV) s_carry[t] = make_float4(0.f, 0.f, 0.f, 0.f);
    }
    __syncthreads();

    // Publish own inclusive prefix (sub==3 threads hold chunk aggregate).
    const float4 carry = s_carry[lane];
    if (sub == NSUB - 1) {
        float4 incl;
        incl.x = carry.x + off.x + a.x;
        incl.y = carry.y + off.y + a.y;
        incl.z = carry.z + off.z + a.z;
        incl.w = carry.w + off.w + a.w;
        g_pref[(b * NC + c) * DV + lane] = incl;
    }
    __threadfence();
    __syncthreads();
    if (t == 0) atomicExch(&g_flag[b * NC + c], 2);

    // Phase 3: re-read the (L2-hot) sub-range, scan, scale, evict-first store.
    float4 run;
    run.x = carry.x + off.x; run.y = carry.y + off.y;
    run.z = carry.z + off.z; run.w = carry.w + off.w;
    float4* q = y + base;
    const float* r = s_recip + sub * SUBLEN;
#pragma unroll 4
    for (int s = 0; s < SUBLEN; ++s) {
        const float4 v = p[(size_t)s * DV];
        run.x += v.x; run.y += v.y; run.z += v.z; run.w += v.w;
        const float rr = r[s];
        float4 o;
        o.x = run.x * rr; o.y = run.y * rr; o.z = run.z * rr; o.w = run.w * rr;
        __stcs(q + (size_t)s * DV, o);
    }
}

extern "C" void kernel_launch(void* const* d_in, const int* in_sizes, int n_in,
                              void* d_out, int out_size) {
    const float4* x = (const float4*)d_in[0];
    float4* y = (float4*)d_out;

    init_state<<<2, 256>>>();
    dim3 grid(NC, B);
    scan_kernel<<<grid, 256>>>(x, y);
}

// round 17
// speedup vs baseline: 1.8274x; 1.7615x over previous
#include <cuda_runtime.h>

// AvgSeq: out[b,s,d] = cumsum_s(x[b,s,d]) / (s+1)
// Fused single-kernel, flat (no-ripple) prefix combine. B=16,S=8192,D=256,fp32.
//
// Grid = (NC=32, B=16) = 512 blocks x 256 threads, all co-resident.
// Every block publishes its chunk-sum BEFORE waiting; then waits for all
// predecessors (they finish ~simultaneously), reduces their sum vectors,
// and emits from the L2-hot input.
//
// NOTE: the flag spin MUST be a strong load (ld.relaxed.gpu), not ld.cg —
// weak flag reads don't synchronize with the producer's fence+flag-write
// (round-16 failure).

#define B 16
#define S 8192
#define D 256
#define DV (D / 4)            // 64 float4 lanes
#define NC 32                 // chunks per batch
#define CLEN (S / NC)         // 256 seq steps per chunk
#define NSUB 4                // sub-ranges per chunk
#define SUBLEN (CLEN / NSUB)  // 64 steps per thread

__device__ float4 g_sum [B * NC * DV];   // per-chunk aggregate vectors
__device__ int    g_flag[B * NC];        // 0 = not ready, 1 = sum published

__global__ void init_state() {
    int i = blockIdx.x * blockDim.x + threadIdx.x;
    if (i < B * NC) g_flag[i] = 0;
}

// STRONG relaxed load (participates in the PTX sync order; ld.cg would not).
__device__ __forceinline__ int ld_flag_strong(const int* p) {
    int v;
    asm volatile("ld.relaxed.gpu.b32 %0, [%1];" : "=r"(v) : "l"(p));
    return v;
}

__global__ void __launch_bounds__(256) scan_kernel(const float4* __restrict__ x,
                                                   float4* __restrict__ y) {
    __shared__ float4 s_part[NSUB][DV];   // per-(sub,lane) sub-range sums
    __shared__ float4 s_carry[DV];        // prefix over predecessor chunks
    __shared__ float  s_recip[CLEN];

    const int t    = threadIdx.x;
    const int lane = t & (DV - 1);
    const int sub  = t >> 6;
    const int c    = blockIdx.x;          // chunk within batch
    const int b    = blockIdx.y;
    const int s0   = c * CLEN;

    s_recip[t] = __fdividef(1.0f, (float)(s0 + t + 1));

    const size_t base =
        ((size_t)b * S + (size_t)s0 + (size_t)sub * SUBLEN) * DV + lane;
    const float4* p = x + base;

    // ── Phase 1: sum this thread's 64-step sub-range (64 x LDG.128). ──
    float4 a = make_float4(0.f, 0.f, 0.f, 0.f);
#pragma unroll 8
    for (int s = 0; s < SUBLEN; ++s) {
        const float4 v = p[(size_t)s * DV];
        a.x += v.x; a.y += v.y; a.z += v.z; a.w += v.w;
    }
    s_part[sub][lane] = a;
    __syncthreads();

    // ── Publish chunk aggregate BEFORE any waiting. ──
    if (sub == 0) {
        float4 tot = s_part[0][lane];
#pragma unroll
        for (int k = 1; k < NSUB; ++k) {
            const float4 q = s_part[k][lane];
            tot.x += q.x; tot.y += q.y; tot.z += q.z; tot.w += q.w;
        }
        g_sum[(b * NC + c) * DV + lane] = tot;
        __threadfence();   // order g_sum store before the flag release
    }
    __syncthreads();
    if (t == 0) atomicExch(&g_flag[b * NC + c], 1);

    // ── Flat wait: lane i<c spins (strong load) on predecessor i's flag. ──
    if (t < c) {
        const int* fp = &g_flag[b * NC + t];
        while (ld_flag_strong(fp) == 0) { }
    }
    __syncthreads();
    __threadfence();   // acquire: flag observations before g_sum reads

    // ── Reduce predecessor sums into the carry (c float4 L2 loads/lane). ──
    if (sub == 0) {
        float4 cs = make_float4(0.f, 0.f, 0.f, 0.f);
        for (int cp = 0; cp < c; ++cp) {
            const float4* src = &g_sum[(b * NC + cp) * DV + lane];
            float4 e;
            asm volatile("ld.global.cg.v4.f32 {%0,%1,%2,%3}, [%4];"
                         : "=f"(e.x), "=f"(e.y), "=f"(e.z), "=f"(e.w)
                         : "l"(src));
            cs.x += e.x; cs.y += e.y; cs.z += e.z; cs.w += e.w;
        }
        s_carry[lane] = cs;
    }
    __syncthreads();

    // ── Intra-chunk exclusive offset + carry. ──
    float4 run = s_carry[lane];
#pragma unroll
    for (int k = 0; k < NSUB; ++k) {
        if (k < sub) {
            const float4 q = s_part[k][lane];
            run.x += q.x; run.y += q.y; run.z += q.z; run.w += q.w;
        }
    }

    // ── Phase 3: re-read (L2-hot) sub-range, scan, scale, evict-first store. ──
    float4* q = y + base;
    const float* r = s_recip + sub * SUBLEN;
#pragma unroll 4
    for (int s = 0; s < SUBLEN; ++s) {
        const float4 v = p[(size_t)s * DV];
        run.x += v.x; run.y += v.y; run.z += v.z; run.w += v.w;
        const float rr = r[s];
        float4 o;
        o.x = run.x * rr; o.y = run.y * rr; o.z = run.z * rr; o.w = run.w * rr;
        __stcs(q + (size_t)s * DV, o);
    }
}

extern "C" void kernel_launch(void* const* d_in, const int* in_sizes, int n_in,
                              void* d_out, int out_size) {
    const float4* x = (const float4*)d_in[0];
    float4* y = (float4*)d_out;

    init_state<<<2, 256>>>();
    dim3 grid(NC, B);
    scan_kernel<<<grid, 256>>>(x, y);
}